// round 1
// baseline (speedup 1.0000x reference)
#include <cuda_runtime.h>
#include <cstdint>

// Problem constants
#define MM      64
#define KK      4096
#define NN      11008
#define GROUP   128
#define NGROUPS 32

// Kernel config
#define THREADS  128
#define BLOCK_N  128              // columns per block (64 col-threads x 2 cols)
#define KSPLIT   8
#define KPB      (KK / KSPLIT)    // 512 k per block
#define GPB      (KPB / GROUP)    // 4 groups per block

// Split-K scratch: KSPLIT * M * N fp32 partials (22.5 MB, static device array)
__device__ float g_partial[KSPLIT * MM * NN];

__device__ __forceinline__ uint64_t fma2(uint64_t a, uint64_t b, uint64_t c) {
    uint64_t d;
    asm("fma.rn.f32x2 %0, %1, %2, %3;" : "=l"(d) : "l"(a), "l"(b), "l"(c));
    return d;
}
__device__ __forceinline__ uint64_t pack2(float lo, float hi) {
    uint64_t r;
    asm("mov.b64 %0, {%1, %2};" : "=l"(r) : "f"(lo), "f"(hi));
    return r;
}
__device__ __forceinline__ void unpack2(uint64_t v, float& lo, float& hi) {
    asm("mov.b64 {%0, %1}, %2;" : "=f"(lo), "=f"(hi) : "l"(v));
}

// Each block: BLOCK_N=128 output columns, all 64 M rows, KPB=512 of K.
// Thread layout: tid[6] selects M-half (rows 0-31 / 32-63); tid[0:5] selects
// a pair of consecutive columns. Accumulators are f32x2 packed over k-parity
// (lo lane = even-k partial sum, hi lane = odd-k partial sum), summed in the
// epilogue. x is staged per 128-k group into smem [m][k] (conflict-free STS,
// broadcast LDS.64 of a k-pair in the inner loop).
__global__ void __launch_bounds__(THREADS)
gemm_partial_kernel(const float* __restrict__ x,
                    const int*   __restrict__ qw,
                    const int*   __restrict__ qz,
                    const float* __restrict__ sc)
{
    __shared__ float xs[MM * GROUP];   // 32 KB, xs[m*GROUP + k_local]

    const int tid  = threadIdx.x;
    const int half = tid >> 6;                       // 0/1 -> m rows
    const int ncol = tid & 63;
    const int n0   = blockIdx.x * BLOCK_N + ncol * 2; // two consecutive columns
    const int m0   = half * 32;
    const int ks   = blockIdx.y * KPB;

    uint64_t acc0[32], acc1[32];
#pragma unroll
    for (int p = 0; p < 32; p++) { acc0[p] = 0ull; acc1[p] = 0ull; }

#pragma unroll 1
    for (int g = 0; g < GPB; g++) {
        const int kg  = ks + g * GROUP;
        const int grp = kg >> 7;                     // group index

        __syncthreads();   // protect previous group's xs reads
        // Stage x[0:64][kg:kg+128] into xs, coalesced float4, conflict-free STS
#pragma unroll
        for (int it = 0; it < (MM * GROUP / 4) / THREADS; it++) {  // 16 iters
            int i = tid + it * THREADS;
            int m = i >> 5;          // 0..63
            int c = i & 31;          // float4 index within the 128-k row
            float4 v = *(const float4*)(x + m * KK + kg + 4 * c);
            *(float4*)(xs + m * GROUP + 4 * c) = v;
        }
        __syncthreads();

        // Per-group, per-column dequant constants: w = q*s - s*(z+1)
        const float s0 = sc[grp * NN + n0];
        const float s1 = sc[grp * NN + n0 + 1];
        const uint32_t zpack = (uint32_t)qz[grp * (NN / 8) + (n0 >> 3)];
        const float z0 = (float)(((zpack >> (4 * (n0 & 7)))       & 15) + 1);
        const float z1 = (float)(((zpack >> (4 * ((n0 + 1) & 7))) & 15) + 1);
        const float off0 = -s0 * z0;
        const float off1 = -s1 * z1;

        const int* qrow = qw + (kg >> 3) * NN;
        // software-prefetched packed-weight loads (2 int32 per 8 k)
        uint32_t q0 = (uint32_t)qrow[n0];
        uint32_t q1 = (uint32_t)qrow[n0 + 1];

#pragma unroll 1
        for (int r = 0; r < GROUP / 8; r++) {        // 16 packed rows / group
            uint32_t nq0 = 0, nq1 = 0;
            if (r < GROUP / 8 - 1) {
                nq0 = (uint32_t)qrow[(r + 1) * NN + n0];
                nq1 = (uint32_t)qrow[(r + 1) * NN + n0 + 1];
            }
#pragma unroll
            for (int jj = 0; jj < 4; jj++) {         // 4 k-pairs per int32
                const int kl = r * 8 + jj * 2;       // local k (even)
                float w00 = (float)((q0 >> (8 * jj))     & 15) * s0 + off0;
                float w01 = (float)((q0 >> (8 * jj + 4)) & 15) * s0 + off0;
                float w10 = (float)((q1 >> (8 * jj))     & 15) * s1 + off1;
                float w11 = (float)((q1 >> (8 * jj + 4)) & 15) * s1 + off1;
                uint64_t w0 = pack2(w00, w01);
                uint64_t w1 = pack2(w10, w11);
                const uint64_t* xrow = (const uint64_t*)(xs + m0 * GROUP + kl);
#pragma unroll
                for (int p = 0; p < 32; p++) {
                    uint64_t xv = xrow[p * (GROUP / 2)];  // broadcast LDS.64
                    acc0[p] = fma2(xv, w0, acc0[p]);
                    acc1[p] = fma2(xv, w1, acc1[p]);
                }
            }
            q0 = nq0;
            q1 = nq1;
        }
    }

    // Epilogue: fold k-parity halves, write fp32 partials
    float* dst = g_partial + (size_t)blockIdx.y * (MM * NN);
#pragma unroll
    for (int p = 0; p < 32; p++) {
        float a0l, a0h, a1l, a1h;
        unpack2(acc0[p], a0l, a0h);
        unpack2(acc1[p], a1l, a1h);
        float2 v = make_float2(a0l + a0h, a1l + a1h);
        *(float2*)(dst + (size_t)(m0 + p) * NN + n0) = v;
    }
}

// out[m][n] = bias[n] + sum_s partial[s][m][n], vectorized float4
__global__ void __launch_bounds__(256)
reduce_bias_kernel(const float* __restrict__ bias, float* __restrict__ out)
{
    const int idx = blockIdx.x * 256 + threadIdx.x;     // float4 index
    const int total = MM * NN / 4;                      // 176128
    if (idx >= total) return;

    float4 s = make_float4(0.f, 0.f, 0.f, 0.f);
#pragma unroll
    for (int sp = 0; sp < KSPLIT; sp++) {
        float4 v = *(const float4*)(g_partial + (size_t)sp * (MM * NN) + idx * 4);
        s.x += v.x; s.y += v.y; s.z += v.z; s.w += v.w;
    }
    const int n = (idx * 4) % NN;                       // NN % 4 == 0
    float4 b = *(const float4*)(bias + n);
    s.x += b.x; s.y += b.y; s.z += b.z; s.w += b.w;
    *(float4*)(out + (size_t)idx * 4) = s;
}

extern "C" void kernel_launch(void* const* d_in, const int* in_sizes, int n_in,
                              void* d_out, int out_size)
{
    const float* x    = (const float*)d_in[0];   // [64, 4096]
    const int*   qw   = (const int*)  d_in[1];   // [512, 11008]
    const int*   qz   = (const int*)  d_in[2];   // [32, 1376]
    const float* sc   = (const float*)d_in[3];   // [32, 11008]
    const float* bias = (const float*)d_in[4];   // [11008]
    float*       out  = (float*)d_out;           // [64, 11008]

    dim3 grid(NN / BLOCK_N, KSPLIT);             // (86, 8)
    gemm_partial_kernel<<<grid, THREADS>>>(x, qw, qz, sc);

    const int total4 = MM * NN / 4;
    reduce_bias_kernel<<<(total4 + 255) / 256, 256>>>(bias, out);
}

// round 5
// speedup vs baseline: 2.1200x; 2.1200x over previous
#include <cuda_runtime.h>
#include <cuda_fp16.h>
#include <cstdint>

// ---------------- problem constants ----------------
#define MM      64
#define KK      4096
#define NN      11008
#define NGROUPS 32

// ---------------- config ----------------
#define NTILE    80            // columns per CTA (last CTA: 48)
#define NCTAS    138           // 137*80 + 48 = 11008, single wave on 148 SMs
#define THREADS  256
#define NT_MAX   10            // n8-tiles per CTA
#define JTOT     256           // k-steps of 16 over K=4096

// A in mma-fragment order: [j 0..255][warp 0..7][lane 0..31] -> uint4 (a0..a3)
// rows: m = 16*w + lane/4 (+8), cols: k = 16*j + 2*(lane%4) (+8); fp16 pairs.
// Rows 0..63 = fp16(x), rows 64..127 = fp16(x - fp16(x)) (hi/lo split).
__device__ uint4 g_afrag[JTOT * 8 * 32];   // 1 MB

// ---------------- kernel 1: build split-A fragments ----------------
__device__ __forceinline__ uint32_t cvt_pair(const float* __restrict__ x, int m, int k) {
    const float* p = x + (size_t)(m < MM ? m : m - MM) * KK + k;
    float2 v = *(const float2*)p;
    __half2 h;
    if (m < MM) {
        h = __floats2half2_rn(v.x, v.y);
    } else {
        __half a = __float2half_rn(v.x), b = __float2half_rn(v.y);
        h = __halves2half2(__float2half_rn(v.x - __half2float(a)),
                           __float2half_rn(v.y - __half2float(b)));
    }
    return *(uint32_t*)&h;
}

__global__ void __launch_bounds__(256)
split_x_kernel(const float* __restrict__ x) {
    int idx  = blockIdx.x * 256 + threadIdx.x;        // 0 .. 65535
    int lane = idx & 31;
    int w    = (idx >> 5) & 7;
    int j    = idx >> 8;
    int m0   = w * 16 + (lane >> 2);
    int k0   = j * 16 + 2 * (lane & 3);
    uint4 r;
    r.x = cvt_pair(x, m0,     k0);
    r.y = cvt_pair(x, m0 + 8, k0);
    r.z = cvt_pair(x, m0,     k0 + 8);
    r.w = cvt_pair(x, m0 + 8, k0 + 8);
    g_afrag[idx] = r;
}

// ---------------- mma.sync helper (plain sm_80+ PTX, no tcgen05) ----------------
__device__ __forceinline__ void mma16816(float* c, const uint4& a, uint32_t b0, uint32_t b1) {
    asm volatile(
        "mma.sync.aligned.m16n8k16.row.col.f32.f16.f16.f32 "
        "{%0,%1,%2,%3}, {%4,%5,%6,%7}, {%8,%9}, {%0,%1,%2,%3};"
        : "+f"(c[0]), "+f"(c[1]), "+f"(c[2]), "+f"(c[3])
        : "r"(a.x), "r"(a.y), "r"(a.z), "r"(a.w), "r"(b0), "r"(b1));
}

// ---------------- kernel 2: fused dequant + HMMA GEMM ----------------
// B fragment smem: Bf[j 0..7][t 0..9][lane] = uint2 {b0, b1}; consumer read is
// lane-indexed LDS.64 (conflict-free). Producer writes 32-bit halves.
__global__ void __launch_bounds__(THREADS)
gemm_kernel(const int*   __restrict__ qw,
            const int*   __restrict__ qz,
            const float* __restrict__ sc,
            const float* __restrict__ bias,
            float*       __restrict__ out)
{
    __shared__ uint2 Bf[8 * NT_MAX * 32];             // 20480 B

    const int tid  = threadIdx.x;
    const int wid  = tid >> 5;
    const int lane = tid & 31;
    const int n0   = blockIdx.x * NTILE;
    const int ncols = (NN - n0 < NTILE) ? (NN - n0) : NTILE;   // 80 or 48
    const int ntc   = ncols >> 3;                              // 10 or 6

    float acc[NT_MAX][4];
#pragma unroll
    for (int t = 0; t < NT_MAX; t++)
#pragma unroll
        for (int i = 0; i < 4; i++) acc[t][i] = 0.f;

#pragma unroll 1
    for (int g = 0; g < NGROUPS; g++) {
        // ---- prefetch this group's A fragments (8 k-steps, L2-resident) ----
        uint4 af[8];
#pragma unroll
        for (int jl = 0; jl < 8; jl++)
            af[jl] = g_afrag[(((g * 8 + jl) * 8) + wid) * 32 + lane];

        // ---- producer: dequant 16 packed rows x ncols int4 -> B fragments ----
#pragma unroll
        for (int i = 0; i < 5; i++) {
            int idx = i * 256 + tid;          // 0..1279
            int r   = idx / 80;               // packed row in group, 0..15
            int n   = idx - r * 80;           // local col
            if (n < ncols) {
                int n_g = n0 + n;
                float s     = __ldg(sc + (size_t)g * NN + n_g);
                uint32_t zp = (uint32_t)__ldg(qz + (size_t)g * (NN / 8) + (n_g >> 3));
                uint32_t q  = (uint32_t)__ldg(qw + (size_t)(g * 16 + r) * NN + n_g);
                int z = (int)((zp >> (4 * (n_g & 7))) & 15) + 1;
                __half2 s2 = __half2half2(__float2half_rn(s));
                __half2 zf = __half2half2(__float2half_rn((float)(1024 + z)));  // exact

                int base = ((r >> 1) * NT_MAX + (n >> 3)) * 32 + 4 * (n & 7);
                int h    = r & 1;
#pragma unroll
                for (int c = 0; c < 4; c++) {
                    uint32_t tq = q >> (8 * c);
                    // fp16x2 {1024+nib_lo, 1024+nib_hi}, exact integers
                    uint32_t v = (tq & 0xFu) | ((tq << 12) & 0xF0000u) | 0x64006400u;
                    __half2 hv = *(__half2*)&v;
                    __half2 wv = __hmul2(__hsub2(hv, zf), s2);   // exact sub, one mul rnd
                    ((uint32_t*)Bf)[(size_t)(base + c) * 2 + h] = *(uint32_t*)&wv;
                }
            }
        }
        __syncthreads();

        // ---- consumer: 8 k-steps x ntc n-tiles of mma.sync ----
#pragma unroll
        for (int jl = 0; jl < 8; jl++) {
#pragma unroll
            for (int t = 0; t < NT_MAX; t++) {
                if (t < ntc) {
                    uint2 bb = Bf[(jl * NT_MAX + t) * 32 + lane];
                    mma16816(acc[t], af[jl], bb.x, bb.y);
                }
            }
        }
        __syncthreads();   // before next group's producer overwrites Bf
    }

    // ---- epilogue: fold hi (rows 0..63) + lo (rows 64..127), add bias ----
    float* Cs = (float*)Bf;                      // 64 x 80 fp32 = 20480 B, reuse
    const int gr  = lane >> 2;
    const int gc2 = 2 * (lane & 3);

    if (wid >= 4) {                              // lo rows -> smem
        int row = (wid - 4) * 16 + gr;
#pragma unroll
        for (int t = 0; t < NT_MAX; t++) {
            if (t < ntc) {
                int col = 8 * t + gc2;
                Cs[row * 80 + col]           = acc[t][0];
                Cs[row * 80 + col + 1]       = acc[t][1];
                Cs[(row + 8) * 80 + col]     = acc[t][2];
                Cs[(row + 8) * 80 + col + 1] = acc[t][3];
            }
        }
    }
    __syncthreads();

    if (wid < 4) {                               // hi rows: add lo + bias, store
        int row = wid * 16 + gr;
#pragma unroll
        for (int t = 0; t < NT_MAX; t++) {
            if (t < ntc) {
                int col = 8 * t + gc2;
                float2 b = *(const float2*)(bias + n0 + col);
                float2 o0, o1;
                o0.x = acc[t][0] + Cs[row * 80 + col]           + b.x;
                o0.y = acc[t][1] + Cs[row * 80 + col + 1]       + b.y;
                o1.x = acc[t][2] + Cs[(row + 8) * 80 + col]     + b.x;
                o1.y = acc[t][3] + Cs[(row + 8) * 80 + col + 1] + b.y;
                *(float2*)(out + (size_t)row * NN + n0 + col)       = o0;
                *(float2*)(out + (size_t)(row + 8) * NN + n0 + col) = o1;
            }
        }
    }
}

extern "C" void kernel_launch(void* const* d_in, const int* in_sizes, int n_in,
                              void* d_out, int out_size)
{
    const float* x    = (const float*)d_in[0];   // [64, 4096]
    const int*   qw   = (const int*)  d_in[1];   // [512, 11008]
    const int*   qz   = (const int*)  d_in[2];   // [32, 1376]
    const float* sc   = (const float*)d_in[3];   // [32, 11008]
    const float* bias = (const float*)d_in[4];   // [11008]
    float*       out  = (float*)d_out;           // [64, 11008]

    split_x_kernel<<<256, 256>>>(x);
    gemm_kernel<<<NCTAS, THREADS>>>(qw, qz, sc, bias, out);
}

// round 6
// speedup vs baseline: 2.3597x; 1.1131x over previous
#include <cuda_runtime.h>
#include <cuda_fp16.h>
#include <cstdint>

// ---------------- problem constants ----------------
#define MM      64
#define KK      4096
#define NN      11008
#define NGROUPS 32

// ---------------- config ----------------
#define NTILE    80            // columns per CTA (last CTA: 48)
#define NCTAS    138           // 137*80 + 48 = 11008, single wave on 148 SMs
#define THREADS  512
#define NT_MAX   10            // n8-tiles per CTA
#define NT_LOC   5             // n8-tiles per warp-group
#define JTOT     256           // k-steps of 16 over K=4096

// A in mma-fragment order: [j 0..255][warp 0..7][lane 0..31] -> uint4 (a0..a3)
// rows: m = 16*w + lane/4 (+8), cols: k = 16*j + 2*(lane%4) (+8); fp16 pairs.
// Rows 0..63 = fp16(x), rows 64..127 = fp16(x - fp16(x)) (hi/lo split).
__device__ uint4 g_afrag[JTOT * 8 * 32];   // 1 MB

// ---------------- kernel 1: build split-A fragments ----------------
__device__ __forceinline__ uint32_t cvt_pair(const float* __restrict__ x, int m, int k) {
    const float* p = x + (size_t)(m < MM ? m : m - MM) * KK + k;
    float2 v = *(const float2*)p;
    __half2 h;
    if (m < MM) {
        h = __floats2half2_rn(v.x, v.y);
    } else {
        __half a = __float2half_rn(v.x), b = __float2half_rn(v.y);
        h = __halves2half2(__float2half_rn(v.x - __half2float(a)),
                           __float2half_rn(v.y - __half2float(b)));
    }
    return *(uint32_t*)&h;
}

__global__ void __launch_bounds__(256)
split_x_kernel(const float* __restrict__ x) {
    int idx  = blockIdx.x * 256 + threadIdx.x;        // 0 .. 65535
    int lane = idx & 31;
    int w    = (idx >> 5) & 7;
    int j    = idx >> 8;
    int m0   = w * 16 + (lane >> 2);
    int k0   = j * 16 + 2 * (lane & 3);
    uint4 r;
    r.x = cvt_pair(x, m0,     k0);
    r.y = cvt_pair(x, m0 + 8, k0);
    r.z = cvt_pair(x, m0,     k0 + 8);
    r.w = cvt_pair(x, m0 + 8, k0 + 8);
    g_afrag[idx] = r;
}

// ---------------- mma.sync helper (plain sm_80+ PTX) ----------------
__device__ __forceinline__ void mma16816(float* c, const uint4& a, uint32_t b0, uint32_t b1) {
    asm volatile(
        "mma.sync.aligned.m16n8k16.row.col.f32.f16.f16.f32 "
        "{%0,%1,%2,%3}, {%4,%5,%6,%7}, {%8,%9}, {%0,%1,%2,%3};"
        : "+f"(c[0]), "+f"(c[1]), "+f"(c[2]), "+f"(c[3])
        : "r"(a.x), "r"(a.y), "r"(a.z), "r"(a.w), "r"(b0), "r"(b1));
}

// ---------------- kernel 2: fused dequant + HMMA GEMM, software-pipelined ----------------
// B fragment smem, double buffered: buffer = [jl 0..7][tg 0..9][lane] uint2.
__global__ void __launch_bounds__(THREADS)
gemm_kernel(const int*   __restrict__ qw,
            const int*   __restrict__ qz,
            const float* __restrict__ sc,
            const float* __restrict__ bias,
            float*       __restrict__ out)
{
    __shared__ uint2 Bf[2 * 8 * NT_MAX * 32];         // 40960 B
    uint32_t* BfW = (uint32_t*)Bf;                    // word view; 5120 words/buffer

    const int tid  = threadIdx.x;
    const int wid  = tid >> 5;
    const int lane = tid & 31;
    const int wm   = wid & 7;                         // m-row group (16 rows)
    const int wg   = wid >> 3;                        // n-tile group (5 tiles)
    const int n0   = blockIdx.x * NTILE;
    const int ncols = (NN - n0 < NTILE) ? (NN - n0) : NTILE;   // 80 or 48
    const int ntc   = ncols >> 3;                              // 10 or 6

    // ---- hoisted producer constants (3 items of 512 covering 16x80) ----
    int  qoff[3], ngl[3], zoff[3], base2[3];
    bool val[3];
#pragma unroll
    for (int i = 0; i < 3; i++) {
        int idx = i * THREADS + tid;
        int r   = idx / 80;
        int n   = idx - r * 80;
        val[i]  = (idx < 1280) && (n < ncols);
        int n_g = n0 + n;
        qoff[i] = r * NN + n_g;
        ngl[i]  = n_g;
        zoff[i] = n_g >> 3;
        base2[i] = (((r >> 1) * NT_MAX + (n >> 3)) * 32 + 4 * (n & 7)) * 2 + (r & 1);
    }

    uint32_t qv[3]; float sv[3]; uint32_t zpv[3];
    auto produce_load = [&](int g) {
#pragma unroll
        for (int i = 0; i < 3; i++) if (val[i]) {
            qv[i]  = (uint32_t)__ldg(qw + (size_t)g * 16 * NN + qoff[i]);
            sv[i]  = __ldg(sc + (size_t)g * NN + ngl[i]);
            zpv[i] = (uint32_t)__ldg(qz + (size_t)g * (NN / 8) + zoff[i]);
        }
    };
    auto produce_alu = [&](int buf) {
#pragma unroll
        for (int i = 0; i < 3; i++) if (val[i]) {
            int z = (int)((zpv[i] >> (4 * (ngl[i] & 7))) & 15) + 1;
            __half2 s2 = __half2half2(__float2half_rn(sv[i]));
            __half2 zf = __half2half2(__float2half_rn((float)(1024 + z)));  // exact int
            uint32_t* dst = BfW + buf * 5120 + base2[i];
#pragma unroll
            for (int c = 0; c < 4; c++) {
                uint32_t tq = qv[i] >> (8 * c);
                uint32_t v  = (tq & 0xFu) | ((tq << 12) & 0xF0000u) | 0x64006400u;
                __half2 wv  = __hmul2(__hsub2(*(__half2*)&v, zf), s2);  // exact sub
                dst[2 * c]  = *(uint32_t*)&wv;
            }
        }
    };

    float acc[NT_LOC][4];
#pragma unroll
    for (int t = 0; t < NT_LOC; t++)
#pragma unroll
        for (int i = 0; i < 4; i++) acc[t][i] = 0.f;

    // ---- prologue: group 0 into buffer 0, A frags for group 0 ----
    produce_load(0);
    produce_alu(0);
    uint4 af[8];
#pragma unroll
    for (int jl = 0; jl < 8; jl++)
        af[jl] = __ldg(&g_afrag[((0 * 8 + jl) * 8 + wm) * 32 + lane]);
    __syncthreads();

#pragma unroll 1
    for (int g = 0; g < NGROUPS; g++) {
        const int buf = g & 1;
        const int gn  = (g + 1 < NGROUPS) ? g + 1 : g;
        const bool has_next = (g + 1 < NGROUPS);

        // issue next group's global loads early (latency hidden behind mma)
        if (has_next) produce_load(gn);
        uint4 afn[8];
#pragma unroll
        for (int jl = 0; jl < 8; jl++)
            afn[jl] = __ldg(&g_afrag[((gn * 8 + jl) * 8 + wm) * 32 + lane]);

        // ---- consume: 8 k-steps x 5 n-tiles per warp ----
#pragma unroll
        for (int jl = 0; jl < 8; jl++) {
#pragma unroll
            for (int tl = 0; tl < NT_LOC; tl++) {
                int tg = wg * NT_LOC + tl;
                if (tg < ntc) {
                    uint2 bb = Bf[((buf * 8 + jl) * NT_MAX + tg) * 32 + lane];
                    mma16816(acc[tl], af[jl], bb.x, bb.y);
                }
            }
        }

        // ---- produce next group into the other buffer ----
        if (has_next) produce_alu(buf ^ 1);
        __syncthreads();
#pragma unroll
        for (int jl = 0; jl < 8; jl++) af[jl] = afn[jl];
    }

    // ---- epilogue: fold hi (rows 0..63) + lo (rows 64..127), add bias ----
    float* Cs = (float*)Bf;                      // 64 x 80 fp32 = 20480 B, reuse
    const int gr  = lane >> 2;
    const int gc2 = 2 * (lane & 3);

    if (wm >= 4) {                               // lo rows -> smem
        int row = (wm - 4) * 16 + gr;
#pragma unroll
        for (int tl = 0; tl < NT_LOC; tl++) {
            int tg = wg * NT_LOC + tl;
            if (tg < ntc) {
                int col = 8 * tg + gc2;
                Cs[row * 80 + col]           = acc[tl][0];
                Cs[row * 80 + col + 1]       = acc[tl][1];
                Cs[(row + 8) * 80 + col]     = acc[tl][2];
                Cs[(row + 8) * 80 + col + 1] = acc[tl][3];
            }
        }
    }
    __syncthreads();

    if (wm < 4) {                                // hi rows: add lo + bias, store
        int row = wm * 16 + gr;
#pragma unroll
        for (int tl = 0; tl < NT_LOC; tl++) {
            int tg = wg * NT_LOC + tl;
            if (tg < ntc) {
                int col = 8 * tg + gc2;
                float2 b = *(const float2*)(bias + n0 + col);
                float2 o0, o1;
                o0.x = acc[tl][0] + Cs[row * 80 + col]           + b.x;
                o0.y = acc[tl][1] + Cs[row * 80 + col + 1]       + b.y;
                o1.x = acc[tl][2] + Cs[(row + 8) * 80 + col]     + b.x;
                o1.y = acc[tl][3] + Cs[(row + 8) * 80 + col + 1] + b.y;
                *(float2*)(out + (size_t)row * NN + n0 + col)       = o0;
                *(float2*)(out + (size_t)(row + 8) * NN + n0 + col) = o1;
            }
        }
    }
}

extern "C" void kernel_launch(void* const* d_in, const int* in_sizes, int n_in,
                              void* d_out, int out_size)
{
    const float* x    = (const float*)d_in[0];   // [64, 4096]
    const int*   qw   = (const int*)  d_in[1];   // [512, 11008]
    const int*   qz   = (const int*)  d_in[2];   // [32, 1376]
    const float* sc   = (const float*)d_in[3];   // [32, 11008]
    const float* bias = (const float*)d_in[4];   // [11008]
    float*       out  = (float*)d_out;           // [64, 11008]

    split_x_kernel<<<256, 256>>>(x);
    gemm_kernel<<<NCTAS, THREADS>>>(qw, qz, sc, bias, out);
}

// round 7
// speedup vs baseline: 2.9312x; 1.2422x over previous
#include <cuda_runtime.h>
#include <cuda_fp16.h>
#include <cstdint>

// ---------------- problem constants ----------------
#define MM      64
#define KK      4096
#define NN      11008
#define NGROUPS 32

// ---------------- config ----------------
#define NTILE    80            // columns per CTA (last CTA: 48)
#define NCTAS    138           // 137*80 + 48 = 11008, single wave on 148 SMs
#define THREADS  512           // 16 warps = 4 m-groups x 4 n-groups
#define NT_MAX   10            // n8-tiles per CTA
#define NT_LOC   3             // max n8-tiles per warp
#define JTOT     256           // k-steps of 16 over K=4096

// A (fp16(x), M=64) in mma-fragment order: [j 0..255][w 0..3][lane] -> uint4.
// rows: m = 16*w + lane/4 (+8), cols: k = 16*j + 2*(lane%4) (+8); fp16 pairs.
__device__ uint4 g_afrag[JTOT * 4 * 32];   // 512 KB

// n-tile partition across the 4 n-groups: {0,1,2},{3,4,5},{6,7},{8,9}
__device__ __constant__ int TSTART[4] = {0, 3, 6, 8};
__device__ __constant__ int TCNT[4]   = {3, 3, 2, 2};

// ---------------- kernel 1: build A fragments ----------------
__device__ __forceinline__ uint32_t cvt_pair(const float* __restrict__ x, int m, int k) {
    float2 v = *(const float2*)(x + (size_t)m * KK + k);
    __half2 h = __floats2half2_rn(v.x, v.y);
    return *(uint32_t*)&h;
}

__global__ void __launch_bounds__(256)
split_x_kernel(const float* __restrict__ x) {
    int idx  = blockIdx.x * 256 + threadIdx.x;        // 0 .. 32767
    int lane = idx & 31;
    int w    = (idx >> 5) & 3;
    int j    = idx >> 7;
    int m0   = w * 16 + (lane >> 2);
    int k0   = j * 16 + 2 * (lane & 3);
    uint4 r;
    r.x = cvt_pair(x, m0,     k0);
    r.y = cvt_pair(x, m0 + 8, k0);
    r.z = cvt_pair(x, m0,     k0 + 8);
    r.w = cvt_pair(x, m0 + 8, k0 + 8);
    g_afrag[idx] = r;
}

// ---------------- mma.sync helper (plain sm_80+ PTX) ----------------
__device__ __forceinline__ void mma16816(float* c, const uint4& a, uint32_t b0, uint32_t b1) {
    asm volatile(
        "mma.sync.aligned.m16n8k16.row.col.f32.f16.f16.f32 "
        "{%0,%1,%2,%3}, {%4,%5,%6,%7}, {%8,%9}, {%0,%1,%2,%3};"
        : "+f"(c[0]), "+f"(c[1]), "+f"(c[2]), "+f"(c[3])
        : "r"(a.x), "r"(a.y), "r"(a.z), "r"(a.w), "r"(b0), "r"(b1));
}

// ---------------- kernel 2: fused dequant + HMMA GEMM, software-pipelined ----------------
// B fragment smem, double buffered: buffer = [jl 0..7][tg 0..9][lane] uint2.
__global__ void __launch_bounds__(THREADS)
gemm_kernel(const int*   __restrict__ qw,
            const int*   __restrict__ qz,
            const float* __restrict__ sc,
            const float* __restrict__ bias,
            float*       __restrict__ out)
{
    __shared__ uint2 Bf[2 * 8 * NT_MAX * 32];         // 40960 B
    uint32_t* BfW = (uint32_t*)Bf;                    // word view; 5120 words/buffer

    const int tid  = threadIdx.x;
    const int wid  = tid >> 5;
    const int lane = tid & 31;
    const int wm   = wid & 3;                         // m-row group (16 rows)
    const int wg   = wid >> 2;                        // n-tile group
    const int tst  = TSTART[wg];
    const int tcn  = TCNT[wg];
    const int n0   = blockIdx.x * NTILE;
    const int ncols = (NN - n0 < NTILE) ? (NN - n0) : NTILE;   // 80 or 48
    const int ntc   = ncols >> 3;                              // 10 or 6

    // ---- hoisted producer constants (3 items of 512 covering 16x80) ----
    int  qoff[3], ngl[3], zoff[3], base2[3];
    bool val[3];
#pragma unroll
    for (int i = 0; i < 3; i++) {
        int idx = i * THREADS + tid;
        int r   = idx / 80;
        int n   = idx - r * 80;
        val[i]  = (idx < 1280) && (n < ncols);
        int n_g = n0 + n;
        qoff[i] = r * NN + n_g;
        ngl[i]  = n_g;
        zoff[i] = n_g >> 3;
        base2[i] = (((r >> 1) * NT_MAX + (n >> 3)) * 32 + 4 * (n & 7)) * 2 + (r & 1);
    }

    uint32_t qv[3]; float sv[3]; uint32_t zpv[3];
    auto produce_load = [&](int g) {
#pragma unroll
        for (int i = 0; i < 3; i++) if (val[i]) {
            qv[i]  = (uint32_t)__ldg(qw + (size_t)g * 16 * NN + qoff[i]);
            sv[i]  = __ldg(sc + (size_t)g * NN + ngl[i]);
            zpv[i] = (uint32_t)__ldg(qz + (size_t)g * (NN / 8) + zoff[i]);
        }
    };
    auto produce_alu = [&](int buf) {
#pragma unroll
        for (int i = 0; i < 3; i++) if (val[i]) {
            int z = (int)((zpv[i] >> (4 * (ngl[i] & 7))) & 15) + 1;
            __half2 s2 = __half2half2(__float2half_rn(sv[i]));
            __half2 zf = __half2half2(__float2half_rn((float)(1024 + z)));  // exact int
            uint32_t* dst = BfW + buf * 5120 + base2[i];
#pragma unroll
            for (int c = 0; c < 4; c++) {
                uint32_t tq = qv[i] >> (8 * c);
                uint32_t v  = (tq & 0xFu) | ((tq << 12) & 0xF0000u) | 0x64006400u;
                __half2 wv  = __hmul2(__hsub2(*(__half2*)&v, zf), s2);  // exact sub
                dst[2 * c]  = *(uint32_t*)&wv;
            }
        }
    };

    float acc[NT_LOC][4];
#pragma unroll
    for (int t = 0; t < NT_LOC; t++)
#pragma unroll
        for (int i = 0; i < 4; i++) acc[t][i] = 0.f;

    // ---- prologue: group 0 into buffer 0, A frags for group 0 ----
    produce_load(0);
    produce_alu(0);
    uint4 af[8];
#pragma unroll
    for (int jl = 0; jl < 8; jl++)
        af[jl] = __ldg(&g_afrag[((0 * 8 + jl) * 4 + wm) * 32 + lane]);
    __syncthreads();

#pragma unroll 1
    for (int g = 0; g < NGROUPS; g++) {
        const int buf = g & 1;
        const int gn  = (g + 1 < NGROUPS) ? g + 1 : g;
        const bool has_next = (g + 1 < NGROUPS);

        // issue next group's global loads early (latency hidden behind mma)
        if (has_next) produce_load(gn);
        uint4 afn[8];
#pragma unroll
        for (int jl = 0; jl < 8; jl++)
            afn[jl] = __ldg(&g_afrag[((gn * 8 + jl) * 4 + wm) * 32 + lane]);

        // ---- consume: 8 k-steps x (<=3) n-tiles per warp ----
#pragma unroll
        for (int jl = 0; jl < 8; jl++) {
#pragma unroll
            for (int tl = 0; tl < NT_LOC; tl++) {
                int tg = tst + tl;
                if (tl < tcn && tg < ntc) {
                    uint2 bb = Bf[((buf * 8 + jl) * NT_MAX + tg) * 32 + lane];
                    mma16816(acc[tl], af[jl], bb.x, bb.y);
                }
            }
        }

        // ---- produce next group into the other buffer ----
        if (has_next) produce_alu(buf ^ 1);
        __syncthreads();
#pragma unroll
        for (int jl = 0; jl < 8; jl++) af[jl] = afn[jl];
    }

    // ---- epilogue: direct store, add bias (no fold needed, M=64) ----
    {
        const int row = wm * 16 + (lane >> 2);
        const int gc2 = 2 * (lane & 3);
#pragma unroll
        for (int tl = 0; tl < NT_LOC; tl++) {
            int tg = tst + tl;
            if (tl < tcn && tg < ntc) {
                int col = 8 * tg + gc2;
                float2 b = *(const float2*)(bias + n0 + col);
                float2 o0, o1;
                o0.x = acc[tl][0] + b.x;
                o0.y = acc[tl][1] + b.y;
                o1.x = acc[tl][2] + b.x;
                o1.y = acc[tl][3] + b.y;
                *(float2*)(out + (size_t)row * NN + n0 + col)       = o0;
                *(float2*)(out + (size_t)(row + 8) * NN + n0 + col) = o1;
            }
        }
    }
}

extern "C" void kernel_launch(void* const* d_in, const int* in_sizes, int n_in,
                              void* d_out, int out_size)
{
    const float* x    = (const float*)d_in[0];   // [64, 4096]
    const int*   qw   = (const int*)  d_in[1];   // [512, 11008]
    const int*   qz   = (const int*)  d_in[2];   // [32, 1376]
    const float* sc   = (const float*)d_in[3];   // [32, 11008]
    const float* bias = (const float*)d_in[4];   // [11008]
    float*       out  = (float*)d_out;           // [64, 11008]

    split_x_kernel<<<128, 256>>>(x);
    gemm_kernel<<<NCTAS, THREADS>>>(qw, qz, sc, bias, out);
}

// round 8
// speedup vs baseline: 3.7647x; 1.2843x over previous
#include <cuda_runtime.h>
#include <cuda_fp16.h>
#include <cstdint>

// ---------------- problem constants ----------------
#define MM      64
#define KK      4096
#define NN      11008
#define NGROUPS 32

// ---------------- config ----------------
#define NTILE    80            // columns per CTA (last CTA: 48)
#define NCTAS    138           // 137*80 + 48 = 11008, single wave on 148 SMs
#define THREADS  512           // 16 warps = 4 m-groups x 4 n-groups
#define NT_MAX   10            // n8-tiles per CTA
#define NT_LOC   3             // max n8-tiles per warp
#define JTOT     256           // k-steps of 16 over K=4096
#define NITEMS   1280          // producer uint4 items per group (8 jl x 10 t x 16)

// A (fp16(x), M=64) in mma-fragment order: [j 0..255][w 0..3][lane] -> uint4.
__device__ uint4 g_afrag[JTOT * 4 * 32];   // 512 KB

// n-tile partition across the 4 n-groups: {0,1,2},{3,4,5},{6,7},{8,9}
__device__ __constant__ int TSTART[4] = {0, 3, 6, 8};
__device__ __constant__ int TCNT[4]   = {3, 3, 2, 2};

// ---------------- kernel 1: build A fragments ----------------
__device__ __forceinline__ uint32_t cvt_pair(const float* __restrict__ x, int m, int k) {
    float2 v = *(const float2*)(x + (size_t)m * KK + k);
    __half2 h = __floats2half2_rn(v.x, v.y);
    return *(uint32_t*)&h;
}

__global__ void __launch_bounds__(256)
split_x_kernel(const float* __restrict__ x) {
    int idx  = blockIdx.x * 256 + threadIdx.x;        // 0 .. 32767
    int lane = idx & 31;
    int w    = (idx >> 5) & 3;
    int j    = idx >> 7;
    int m0   = w * 16 + (lane >> 2);
    int k0   = j * 16 + 2 * (lane & 3);
    uint4 r;
    r.x = cvt_pair(x, m0,     k0);
    r.y = cvt_pair(x, m0 + 8, k0);
    r.z = cvt_pair(x, m0,     k0 + 8);
    r.w = cvt_pair(x, m0 + 8, k0 + 8);
    g_afrag[idx] = r;
}

// ---------------- mma.sync helper (plain sm_80+ PTX) ----------------
__device__ __forceinline__ void mma16816(float* c, const uint4& a, uint32_t b0, uint32_t b1) {
    asm volatile(
        "mma.sync.aligned.m16n8k16.row.col.f32.f16.f16.f32 "
        "{%0,%1,%2,%3}, {%4,%5,%6,%7}, {%8,%9}, {%0,%1,%2,%3};"
        : "+f"(c[0]), "+f"(c[1]), "+f"(c[2]), "+f"(c[3])
        : "r"(a.x), "r"(a.y), "r"(a.z), "r"(a.w), "r"(b0), "r"(b1));
}

// dequant pair c (nibbles 2c,2c+1) of packed word q -> fp16x2, exact-int path
__device__ __forceinline__ uint32_t dq_pair(uint32_t q, int c8, __half2 zf, __half2 s2) {
    uint32_t tq = q >> c8;
    uint32_t v  = (tq & 0xFu) | ((tq << 12) & 0xF0000u) | 0x64006400u;
    __half2 wv  = __hmul2(__hsub2(*(__half2*)&v, zf), s2);
    return *(uint32_t*)&wv;
}

// ---------------- kernel 2: fused dequant + HMMA GEMM, software-pipelined ----------------
// B fragment smem, double buffered. Consumer view: uint2 Bf[buf][jl][tg][lane].
// Producer view: uint4 Bf4[buf][e], e = (jl*NT_MAX + tg)*16 + L covering the
// consumer uint2s of lanes 2L, 2L+1 -> one coalesced conflict-free STS.128.
__global__ void __launch_bounds__(THREADS)
gemm_kernel(const int*   __restrict__ qw,
            const int*   __restrict__ qz,
            const float* __restrict__ sc,
            const float* __restrict__ bias,
            float*       __restrict__ out)
{
    __shared__ uint2 Bf[2 * 8 * NT_MAX * 32];         // 40960 B
    uint4* Bf4 = (uint4*)Bf;                          // 2 x 1280 uint4

    const int tid  = threadIdx.x;
    const int wid  = tid >> 5;
    const int lane = tid & 31;
    const int wm   = wid & 3;                         // m-row group (16 rows)
    const int wg   = wid >> 2;                        // n-tile group
    const int tst  = TSTART[wg];
    const int tcn  = TCNT[wg];
    const int n0   = blockIdx.x * NTILE;
    const int ncols = (NN - n0 < NTILE) ? (NN - n0) : NTILE;   // 80 or 48
    const int ntc   = ncols >> 3;                              // 10 or 6

    // ---- hoisted producer constants (3 items of 512 covering 1280) ----
    int  ei[3], qoff0[3], ngl[3], c8[3], zsh[3];
    bool val[3];
#pragma unroll
    for (int i = 0; i < 3; i++) {
        int e  = i * THREADS + tid;
        int u  = e >> 4;                  // (jl, tile) unit
        int L  = e & 15;                  // lane-pair
        int jl = u / NT_MAX;
        int t  = u - jl * NT_MAX;
        int n  = 8 * t + (L >> 1);        // local column
        val[i] = (e < NITEMS) && (n < ncols);
        int n_g = n0 + n;
        ei[i]    = e;
        ngl[i]   = n_g;
        qoff0[i] = 2 * jl * NN + n_g;     // row 2*jl of group, col n_g
        c8[i]    = 8 * (2 * (L & 1));     // shift for pair c0 = 2*(L&1)
        zsh[i]   = 4 * (n_g & 7);
    }

    uint32_t qv0[3], qv1[3], zpv[3]; float sv[3];
    auto produce_load = [&](int g) {
#pragma unroll
        for (int i = 0; i < 3; i++) if (val[i]) {
            const int* qp = qw + (size_t)g * 16 * NN + qoff0[i];
            qv0[i] = (uint32_t)__ldg(qp);
            qv1[i] = (uint32_t)__ldg(qp + NN);
            sv[i]  = __ldg(sc + (size_t)g * NN + ngl[i]);
            zpv[i] = (uint32_t)__ldg(qz + (size_t)g * (NN / 8) + (ngl[i] >> 3));
        }
    };
    auto produce_alu = [&](int buf) {
#pragma unroll
        for (int i = 0; i < 3; i++) if (val[i]) {
            int z = (int)((zpv[i] >> zsh[i]) & 15) + 1;
            __half2 s2 = __half2half2(__float2half_rn(sv[i]));
            __half2 zf = __half2half2(__float2half_rn((float)(1024 + z)));  // exact int
            uint4 o;
            o.x = dq_pair(qv0[i], c8[i],     zf, s2);   // lane 2L,   b0 (row 2jl)
            o.y = dq_pair(qv1[i], c8[i],     zf, s2);   // lane 2L,   b1 (row 2jl+1)
            o.z = dq_pair(qv0[i], c8[i] + 8, zf, s2);   // lane 2L+1, b0
            o.w = dq_pair(qv1[i], c8[i] + 8, zf, s2);   // lane 2L+1, b1
            Bf4[buf * NITEMS + ei[i]] = o;              // coalesced STS.128
        }
    };

    float acc[NT_LOC][4];
#pragma unroll
    for (int t = 0; t < NT_LOC; t++)
#pragma unroll
        for (int i = 0; i < 4; i++) acc[t][i] = 0.f;

    // ---- prologue: group 0 into buffer 0, A frags for group 0 ----
    produce_load(0);
    produce_alu(0);
    uint4 af[8];
#pragma unroll
    for (int jl = 0; jl < 8; jl++)
        af[jl] = __ldg(&g_afrag[((0 * 8 + jl) * 4 + wm) * 32 + lane]);
    __syncthreads();

#pragma unroll 1
    for (int g = 0; g < NGROUPS; g++) {
        const int buf = g & 1;
        const int gn  = (g + 1 < NGROUPS) ? g + 1 : g;
        const bool has_next = (g + 1 < NGROUPS);

        // issue next group's global loads early (latency hidden behind mma)
        if (has_next) produce_load(gn);
        uint4 afn[8];
#pragma unroll
        for (int jl = 0; jl < 8; jl++)
            afn[jl] = __ldg(&g_afrag[((gn * 8 + jl) * 4 + wm) * 32 + lane]);

        // ---- consume: 8 k-steps x (<=3) n-tiles per warp ----
#pragma unroll
        for (int jl = 0; jl < 8; jl++) {
#pragma unroll
            for (int tl = 0; tl < NT_LOC; tl++) {
                int tg = tst + tl;
                if (tl < tcn && tg < ntc) {
                    uint2 bb = Bf[((buf * 8 + jl) * NT_MAX + tg) * 32 + lane];
                    mma16816(acc[tl], af[jl], bb.x, bb.y);
                }
            }
        }

        // ---- produce next group into the other buffer ----
        if (has_next) produce_alu(buf ^ 1);
        __syncthreads();
#pragma unroll
        for (int jl = 0; jl < 8; jl++) af[jl] = afn[jl];
    }

    // ---- epilogue: direct store, add bias ----
    {
        const int row = wm * 16 + (lane >> 2);
        const int gc2 = 2 * (lane & 3);
#pragma unroll
        for (int tl = 0; tl < NT_LOC; tl++) {
            int tg = tst + tl;
            if (tl < tcn && tg < ntc) {
                int col = 8 * tg + gc2;
                float2 b = *(const float2*)(bias + n0 + col);
                float2 o0, o1;
                o0.x = acc[tl][0] + b.x;
                o0.y = acc[tl][1] + b.y;
                o1.x = acc[tl][2] + b.x;
                o1.y = acc[tl][3] + b.y;
                *(float2*)(out + (size_t)row * NN + n0 + col)       = o0;
                *(float2*)(out + (size_t)(row + 8) * NN + n0 + col) = o1;
            }
        }
    }
}

extern "C" void kernel_launch(void* const* d_in, const int* in_sizes, int n_in,
                              void* d_out, int out_size)
{
    const float* x    = (const float*)d_in[0];   // [64, 4096]
    const int*   qw   = (const int*)  d_in[1];   // [512, 11008]
    const int*   qz   = (const int*)  d_in[2];   // [32, 1376]
    const float* sc   = (const float*)d_in[3];   // [32, 11008]
    const float* bias = (const float*)d_in[4];   // [11008]
    float*       out  = (float*)d_out;           // [64, 11008]

    split_x_kernel<<<128, 256>>>(x);
    gemm_kernel<<<NCTAS, THREADS>>>(qw, qz, sc, bias, out);
}